// round 15
// baseline (speedup 1.0000x reference)
#include <cuda_runtime.h>
#include <cuda_bf16.h>
#include <cstdint>

#define B_  16
#define P_  2048
#define H_  128
#define K_  8
#define NPTS (B_ * P_)
#define NTILE 32              // P_/64 candidate tiles per batch
#define NPAIR 528             // NTILE*(NTILE+1)/2

// ---------------- scratch (no allocations allowed) ----------------
__device__ float  g_x1[NPTS * H_];
__device__ float  g_x2[NPTS * H_];
__device__ float  g_x3[NPTS * H_];
__device__ float  g_T [NPTS * H_];
__device__ float  g_Y [NPTS * H_];
__device__ float  g_sq[NPTS];
__device__ int    g_idx[NPTS * K_];
__device__ float2 g_part[(size_t)NPTS * NTILE * K_];   // per (query, tile) partial top-8
__device__ float  g_poolp[B_ * 8 * 3 * H_];
__device__ float  g_pool[B_ * 3 * H_];

// ---------------- top-8 (smallest d2, tie -> lower index) ----------------
__device__ __forceinline__ void top8_init(float* bd, int* bi) {
#pragma unroll
    for (int m = 0; m < 8; m++) { bd[m] = __int_as_float(0x7f800000); bi[m] = 0x7fffffff; }
}

__device__ __forceinline__ void top8_insert(float* bd, int* bi, float d, int j) {
    if (d < bd[7] || (d == bd[7] && j < bi[7])) {
        bd[7] = d; bi[7] = j;
#pragma unroll
        for (int m = 7; m > 0; m--) {
            bool sw = (bd[m] < bd[m - 1]) || (bd[m] == bd[m - 1] && bi[m] < bi[m - 1]);
            if (!sw) break;
            float td = bd[m]; bd[m] = bd[m - 1]; bd[m - 1] = td;
            int   tj = bi[m]; bi[m] = bi[m - 1]; bi[m - 1] = tj;
        }
    }
}

// ---------------- fp32 -> bf16 hi/lo split (4 values -> uint2 hi, uint2 lo) ----
__device__ __forceinline__ void cvt_hilo4(float4 v, uint2& hi, uint2& lo) {
    __nv_bfloat162 h0 = __floats2bfloat162_rn(v.x, v.y);
    __nv_bfloat162 h1 = __floats2bfloat162_rn(v.z, v.w);
    __nv_bfloat162 l0 = __floats2bfloat162_rn(v.x - __bfloat162float(h0.x),
                                              v.y - __bfloat162float(h0.y));
    __nv_bfloat162 l1 = __floats2bfloat162_rn(v.z - __bfloat162float(h1.x),
                                              v.w - __bfloat162float(h1.y));
    hi.x = *(uint32_t*)&h0; hi.y = *(uint32_t*)&h1;
    lo.x = *(uint32_t*)&l0; lo.y = *(uint32_t*)&l1;
}

// ---------------- squared norms (one warp per point) ----------------
__global__ void sqnorm_kernel(const float* __restrict__ X, float* __restrict__ sq,
                              int D, int npts) {
    int gw = (blockIdx.x * blockDim.x + threadIdx.x) >> 5;
    int lane = threadIdx.x & 31;
    if (gw >= npts) return;
    const float* xp = X + (size_t)gw * D;
    float s = 0.f;
    for (int d = lane; d < D; d += 32) { float v = xp[d]; s = fmaf(v, v, s); }
#pragma unroll
    for (int o = 16; o > 0; o >>= 1) s += __shfl_xor_sync(0xffffffffu, s, o);
    if (lane == 0) sq[gw] = s;
}

// ---------------- kNN for D=3 (one thread per query) ----------------
__global__ __launch_bounds__(256) void knn3_kernel(const float* __restrict__ X,
                                                   const float* __restrict__ sq,
                                                   int* __restrict__ idx) {
    int b = blockIdx.y;
    int q = blockIdx.x * 256 + threadIdx.x;
    const float* Xb  = X  + (size_t)b * P_ * 3;
    const float* sqb = sq + (size_t)b * P_;
    float qx = Xb[q * 3 + 0], qy = Xb[q * 3 + 1], qz = Xb[q * 3 + 2];
    float sqq = sqb[q];
    float bd[8]; int bi[8]; top8_init(bd, bi);
    __shared__ float cs[256][4];
    for (int t = 0; t < P_; t += 256) {
        int tt = threadIdx.x;
        cs[tt][0] = Xb[(t + tt) * 3 + 0];
        cs[tt][1] = Xb[(t + tt) * 3 + 1];
        cs[tt][2] = Xb[(t + tt) * 3 + 2];
        cs[tt][3] = sqb[t + tt];
        __syncthreads();
        for (int jj = 0; jj < 256; jj++) {
            float dot = qx * cs[jj][0] + qy * cs[jj][1] + qz * cs[jj][2];
            float d = sqq + cs[jj][3] - 2.f * dot;
            top8_insert(bd, bi, d, t + jj);
        }
        __syncthreads();
    }
    int* op = idx + ((size_t)b * P_ + q) * K_;
#pragma unroll
    for (int m = 0; m < 8; m++) op[m] = bi[m];
}

// ---------------- symmetric kNN for D=128, dot phase via mma.sync ----------------
// One block per unordered tile pair (qt <= ct). 64x64 dot tile via split-bf16 3-MMA
// (Ahi*Bhi + Ahi*Blo + Alo*Bhi, fp32 acc). Scan both triangles, write partial
// top-8 per (query, tile) to g_part; merge kernel finishes.
// smem bytes: Qhi|Qlo|Chi|Clo [64x136 bf16 each] | d2s[64x65 f32] | qsq | csq
// merge buffers md/mi overlay Qhi (dead after the MMA phase).
#define STRA 68     // uint32 words per smem row (136 bf16)
#define KNN_SMEM_BYTES (4 * 64 * 136 * 2 + 64 * 65 * 4 + 64 * 4 + 64 * 4)
__global__ __launch_bounds__(256) void knn128_sym_kernel(const float* __restrict__ X,
                                                         const float* __restrict__ sq) {
    extern __shared__ float sm[];
    __nv_bfloat16* Qhi = (__nv_bfloat16*)sm;
    __nv_bfloat16* Qlo = Qhi + 64 * 136;
    __nv_bfloat16* Chi = Qlo + 64 * 136;
    __nv_bfloat16* Clo = Chi + 64 * 136;
    float* d2s = (float*)(Clo + 64 * 136);     // [q][c] stride 65 (holds dot)
    float* qsq = d2s + 64 * 65;
    float* csq = qsq + 64;
    float* md  = sm;                           // overlay: 2048 floats (8KB)
    int*   mi  = (int*)(sm + 2048);            // overlay: 2048 ints  (8KB)

    int b = blockIdx.y;
    int lin = blockIdx.x, qt = 0;
    while (true) { int cnt = NTILE - qt; if (lin < cnt) break; lin -= cnt; qt++; }
    int ct = qt + lin;
    int q0 = qt * 64, c0 = ct * 64;

    int tid = threadIdx.x;
    const float* Xb  = X  + (size_t)b * P_ * 128;
    const float* sqb = sq + (size_t)b * P_;

    // ---- load + hi/lo convert Q and C tiles (k-contiguous rows, 136-pad) ----
    {
        int r = tid >> 2, seg = tid & 3;       // 64 rows x 4 segs of 32 dims
        const float4* qsrc = (const float4*)(Xb + (size_t)(q0 + r) * 128 + seg * 32);
        const float4* csrc = (const float4*)(Xb + (size_t)(c0 + r) * 128 + seg * 32);
        uint2* qh = (uint2*)(Qhi + r * 136 + seg * 32);
        uint2* ql = (uint2*)(Qlo + r * 136 + seg * 32);
        uint2* ch = (uint2*)(Chi + r * 136 + seg * 32);
        uint2* cl = (uint2*)(Clo + r * 136 + seg * 32);
#pragma unroll
        for (int u = 0; u < 8; u++) {
            uint2 hi, lo;
            cvt_hilo4(qsrc[u], hi, lo); qh[u] = hi; ql[u] = lo;
            cvt_hilo4(csrc[u], hi, lo); ch[u] = hi; cl[u] = lo;
        }
    }
    if (tid < 64)       qsq[tid]      = sqb[q0 + tid];
    else if (tid < 128) csq[tid - 64] = sqb[c0 + tid - 64];
    __syncthreads();

    // ---- MMA dot phase: warp (mt, nh) -> rows mt*16..+15, cols nh*32..+31 ----
    {
        int warp = tid >> 5, lane = tid & 31;
        int g = lane >> 2, tig = lane & 3;
        int mt = warp & 3, nh = warp >> 2;
        int r0 = mt * 16, c0w = nh * 32;
        const uint32_t* QH = (const uint32_t*)Qhi;
        const uint32_t* QL = (const uint32_t*)Qlo;
        const uint32_t* CH = (const uint32_t*)Chi;
        const uint32_t* CL = (const uint32_t*)Clo;

        float acc[4][4];
#pragma unroll
        for (int nt = 0; nt < 4; nt++)
#pragma unroll
            for (int i = 0; i < 4; i++) acc[nt][i] = 0.f;

#pragma unroll 1
        for (int s = 0; s < 3; s++) {
            const uint32_t* A  = (s == 2) ? QL : QH;
            const uint32_t* Bm = (s == 1) ? CL : CH;
#pragma unroll
            for (int kt = 0; kt < 8; kt++) {
                uint32_t a0 = A[(r0 + g)     * STRA + 8 * kt + tig];
                uint32_t a1 = A[(r0 + g + 8) * STRA + 8 * kt + tig];
                uint32_t a2 = A[(r0 + g)     * STRA + 8 * kt + 4 + tig];
                uint32_t a3 = A[(r0 + g + 8) * STRA + 8 * kt + 4 + tig];
#pragma unroll
                for (int nt = 0; nt < 4; nt++) {
                    int brow = c0w + 8 * nt + g;
                    uint32_t b0 = Bm[brow * STRA + 8 * kt + tig];
                    uint32_t b1 = Bm[brow * STRA + 8 * kt + 4 + tig];
                    asm volatile(
                        "mma.sync.aligned.m16n8k16.row.col.f32.bf16.bf16.f32 "
                        "{%0,%1,%2,%3}, {%4,%5,%6,%7}, {%8,%9}, {%0,%1,%2,%3};"
                        : "+f"(acc[nt][0]), "+f"(acc[nt][1]),
                          "+f"(acc[nt][2]), "+f"(acc[nt][3])
                        : "r"(a0), "r"(a1), "r"(a2), "r"(a3), "r"(b0), "r"(b1));
                }
            }
        }
        // dump dot fragments: row = m (query), col = n (candidate)
#pragma unroll
        for (int nt = 0; nt < 4; nt++) {
            int cb = c0w + nt * 8 + 2 * tig;
            d2s[(r0 + g)     * 65 + cb]     = acc[nt][0];
            d2s[(r0 + g)     * 65 + cb + 1] = acc[nt][1];
            d2s[(r0 + g + 8) * 65 + cb]     = acc[nt][2];
            d2s[(r0 + g + 8) * 65 + cb + 1] = acc[nt][3];
        }
    }
    __syncthreads();   // Q/C smem dead from here; overlay md/mi

    int q_s = tid >> 2, sl = tid & 3;          // 4 lanes per query

    // ---- row phase: queries q0+q_s, candidates c0+c ----
    {
        float bd[8]; int bi8[8]; top8_init(bd, bi8);
        float sqq = qsq[q_s];
#pragma unroll
        for (int u = 0; u < 16; u++) {
            int c = sl * 16 + u;
            float d = sqq + csq[c] - 2.f * d2s[q_s * 65 + c];
            top8_insert(bd, bi8, d, c0 + c);
        }
        int base = q_s * 32 + sl * 8;
#pragma unroll
        for (int m = 0; m < 8; m++) { md[base + m] = bd[m]; mi[base + m] = bi8[m]; }
    }
    __syncthreads();
    if (sl == 0) {
        float fd[8]; int fi[8]; top8_init(fd, fi);
        for (int e = 0; e < 32; e++) top8_insert(fd, fi, md[q_s * 32 + e], mi[q_s * 32 + e]);
        float2* gp = g_part + ((size_t)(b * P_ + q0 + q_s) * NTILE + ct) * K_;
#pragma unroll
        for (int m = 0; m < 8; m++) gp[m] = make_float2(fd[m], __int_as_float(fi[m]));
    }

    // ---- col phase (skip diagonal): queries c0+q_s, candidates q0+r ----
    if (ct != qt) {
        __syncthreads();
        {
            float bd[8]; int bi8[8]; top8_init(bd, bi8);
            float sqq = csq[q_s];
#pragma unroll
            for (int u = 0; u < 16; u++) {
                int r = sl * 16 + u;
                float d = sqq + qsq[r] - 2.f * d2s[r * 65 + q_s];
                top8_insert(bd, bi8, d, q0 + r);
            }
            int base = q_s * 32 + sl * 8;
#pragma unroll
            for (int m = 0; m < 8; m++) { md[base + m] = bd[m]; mi[base + m] = bi8[m]; }
        }
        __syncthreads();
        if (sl == 0) {
            float fd[8]; int fi[8]; top8_init(fd, fi);
            for (int e = 0; e < 32; e++) top8_insert(fd, fi, md[q_s * 32 + e], mi[q_s * 32 + e]);
            float2* gp = g_part + ((size_t)(b * P_ + c0 + q_s) * NTILE + qt) * K_;
#pragma unroll
            for (int m = 0; m < 8; m++) gp[m] = make_float2(fd[m], __int_as_float(fi[m]));
        }
    }
}

// ---------------- merge partial top-8 lists ----------------
__global__ __launch_bounds__(256) void knnmerge_kernel(int* __restrict__ idx) {
    int q = blockIdx.x * 256 + threadIdx.x;
    const float2* pp = g_part + (size_t)q * (NTILE * K_);
    float bd[8]; int bi8[8]; top8_init(bd, bi8);
    for (int e = 0; e < NTILE * K_; e++) {
        float2 v = pp[e];
        top8_insert(bd, bi8, v.x, __float_as_int(v.y));
    }
    int* op = idx + (size_t)q * K_;
#pragma unroll
    for (int m = 0; m < 8; m++) op[m] = bi8[m];
}

// ---------------- pretransform, D=3 ----------------
__global__ __launch_bounds__(256) void pre3_kernel(const float* __restrict__ x,
                                                   const float* __restrict__ W1,
                                                   const float* __restrict__ b1,
                                                   float* __restrict__ T,
                                                   float* __restrict__ Y) {
    int p = blockIdx.x * 8 + (threadIdx.x >> 5);
    int l = threadIdx.x & 31;
    const float4* W14 = (const float4*)W1;
    float4 t = ((const float4*)b1)[l];
    float4 y = {0.f, 0.f, 0.f, 0.f};
#pragma unroll
    for (int r = 0; r < 3; r++) {
        float  xr  = x[p * 3 + r];
        float4 whi = W14[r * 32 + l];
        float4 wlo = W14[(3 + r) * 32 + l];
        t.x = fmaf(xr, whi.x - wlo.x, t.x); t.y = fmaf(xr, whi.y - wlo.y, t.y);
        t.z = fmaf(xr, whi.z - wlo.z, t.z); t.w = fmaf(xr, whi.w - wlo.w, t.w);
        y.x = fmaf(xr, wlo.x, y.x); y.y = fmaf(xr, wlo.y, y.y);
        y.z = fmaf(xr, wlo.z, y.z); y.w = fmaf(xr, wlo.w, y.w);
    }
    ((float4*)T)[p * 32 + l] = t;
    ((float4*)Y)[p * 32 + l] = y;
}

// ---------------- pretransform, D=128 (unchanged) ----------------
#define PRE_SMEM_FLOATS (16384 + 16384 + 16 * 1024)
__global__ __launch_bounds__(512) void pre128_kernel(const float* __restrict__ xin,
                                                     const float* __restrict__ W1,
                                                     const float* __restrict__ b1,
                                                     float* __restrict__ T,
                                                     float* __restrict__ Y) {
    extern __shared__ float sm[];
    float* Wds  = sm;
    float* Wlos = Wds + 16384;
    float* Xs   = Wlos + 16384;
    int tid = threadIdx.x;
    int warp = tid >> 5, lane = tid & 31;

    for (int e = tid; e < 16384; e += 512) {
        float hi = W1[e], lo = W1[16384 + e];
        Wds[e] = hi - lo; Wlos[e] = lo;
    }
    int p0 = blockIdx.x * 128 + warp * 8;
    float4* Xw4 = (float4*)(Xs + warp * 1024);
#pragma unroll
    for (int e = 0; e < 8; e++)
        Xw4[e * 32 + lane] = ((const float4*)xin)[(size_t)(p0 + e) * 32 + lane];
    __syncthreads();

    const float4* Wd4  = (const float4*)Wds;
    const float4* Wl4  = (const float4*)Wlos;
    const float4* Xf4  = (const float4*)(Xs + warp * 1024);

#pragma unroll 1
    for (int pass = 0; pass < 2; pass++) {
        const float4* W4 = pass ? Wl4 : Wd4;
        float4 acc[8];
#pragma unroll
        for (int e = 0; e < 8; e++) acc[e] = make_float4(0.f, 0.f, 0.f, 0.f);
        for (int d0 = 0; d0 < 128; d0 += 4) {
            float4 w0 = W4[(d0 + 0) * 32 + lane];
            float4 w1 = W4[(d0 + 1) * 32 + lane];
            float4 w2 = W4[(d0 + 2) * 32 + lane];
            float4 w3 = W4[(d0 + 3) * 32 + lane];
#pragma unroll
            for (int e = 0; e < 8; e++) {
                float4 h = Xf4[e * 32 + (d0 >> 2)];
                acc[e].x = fmaf(h.x, w0.x, acc[e].x); acc[e].y = fmaf(h.x, w0.y, acc[e].y);
                acc[e].z = fmaf(h.x, w0.z, acc[e].z); acc[e].w = fmaf(h.x, w0.w, acc[e].w);
                acc[e].x = fmaf(h.y, w1.x, acc[e].x); acc[e].y = fmaf(h.y, w1.y, acc[e].y);
                acc[e].z = fmaf(h.y, w1.z, acc[e].z); acc[e].w = fmaf(h.y, w1.w, acc[e].w);
                acc[e].x = fmaf(h.z, w2.x, acc[e].x); acc[e].y = fmaf(h.z, w2.y, acc[e].y);
                acc[e].z = fmaf(h.z, w2.z, acc[e].z); acc[e].w = fmaf(h.z, w2.w, acc[e].w);
                acc[e].x = fmaf(h.w, w3.x, acc[e].x); acc[e].y = fmaf(h.w, w3.y, acc[e].y);
                acc[e].z = fmaf(h.w, w3.z, acc[e].z); acc[e].w = fmaf(h.w, w3.w, acc[e].w);
            }
        }
        if (pass == 0) {
            float4 bb = ((const float4*)b1)[lane];
#pragma unroll
            for (int e = 0; e < 8; e++) {
                float4 o; o.x = acc[e].x + bb.x; o.y = acc[e].y + bb.y;
                o.z = acc[e].z + bb.z; o.w = acc[e].w + bb.w;
                ((float4*)T)[(size_t)(p0 + e) * 32 + lane] = o;
            }
        } else {
#pragma unroll
            for (int e = 0; e < 8; e++)
                ((float4*)Y)[(size_t)(p0 + e) * 32 + lane] = acc[e];
        }
    }
}

// ---------------- edge MLP2 via warp-level mma.sync (split-bf16 x3, unchanged) ----
#define EDGE_SMEM_BYTES (1024 + 4 * 128 * STRA * 4)   // sidx+b2 | W2hi W2lo H1hi H1lo
__global__ __launch_bounds__(256) void edgemma_kernel(const float* __restrict__ T,
                                                      const float* __restrict__ Y,
                                                      const int* __restrict__ idx,
                                                      const float* __restrict__ W2,
                                                      const float* __restrict__ b2,
                                                      float* __restrict__ xout) {
    extern __shared__ float sm[];
    int*      sidx = (int*)sm;                    // 128 ints
    float*    b2s  = sm + 128;                    // 128 floats
    uint32_t* W2hi = (uint32_t*)(sm + 256);       // [c][k] 128 x 68 words
    uint32_t* W2lo = W2hi + 128 * STRA;
    uint32_t* H1hi = W2lo + 128 * STRA;           // [r][k]
    uint32_t* H1lo = H1hi + 128 * STRA;

    int tid = threadIdx.x, warp = tid >> 5, lane = tid & 31;
    int g = lane >> 2, tig = lane & 3;

    if (tid < 128) b2s[tid] = b2[tid];
    for (int e = tid; e < 16384; e += 256) {
        int d = e >> 7, c = e & 127;
        float v = W2[e];
        __nv_bfloat16 bh = __float2bfloat16(v);
        __nv_bfloat16 bl = __float2bfloat16(v - __bfloat162float(bh));
        ((__nv_bfloat16*)W2hi)[c * 136 + d] = bh;
        ((__nv_bfloat16*)W2lo)[c * 136 + d] = bl;
    }
    __syncthreads();

#pragma unroll 1
    for (int tile = blockIdx.x; tile < NPTS / 16; tile += gridDim.x) {
        if (tid < 128) sidx[tid] = idx[tile * 128 + tid];
        __syncthreads();

        {
            int r = tid >> 1, half = tid & 1;
            int j = sidx[r];
            int p = tile * 16 + (r >> 3);
            int base = p & ~(P_ - 1);
            const float4* Tp = (const float4*)(T + (size_t)p * 128 + half * 64);
            const float4* Yp = (const float4*)(Y + (size_t)(base + j) * 128 + half * 64);
            uint4* oh = (uint4*)((__nv_bfloat16*)H1hi + r * 136 + half * 64);
            uint4* ol = (uint4*)((__nv_bfloat16*)H1lo + r * 136 + half * 64);
#pragma unroll
            for (int u = 0; u < 8; u++) {
                float4 ta = Tp[2 * u], tb = Tp[2 * u + 1];
                float4 ya = Yp[2 * u], yb = Yp[2 * u + 1];
                float h0 = fmaxf(ta.x + ya.x, 0.f), h1 = fmaxf(ta.y + ya.y, 0.f);
                float h2 = fmaxf(ta.z + ya.z, 0.f), h3 = fmaxf(ta.w + ya.w, 0.f);
                float h4 = fmaxf(tb.x + yb.x, 0.f), h5 = fmaxf(tb.y + yb.y, 0.f);
                float h6 = fmaxf(tb.z + yb.z, 0.f), h7 = fmaxf(tb.w + yb.w, 0.f);
                __nv_bfloat162 p01 = __floats2bfloat162_rn(h0, h1);
                __nv_bfloat162 p23 = __floats2bfloat162_rn(h2, h3);
                __nv_bfloat162 p45 = __floats2bfloat162_rn(h4, h5);
                __nv_bfloat162 p67 = __floats2bfloat162_rn(h6, h7);
                uint4 hi4;
                hi4.x = *(uint32_t*)&p01; hi4.y = *(uint32_t*)&p23;
                hi4.z = *(uint32_t*)&p45; hi4.w = *(uint32_t*)&p67;
                __nv_bfloat162 q01 = __floats2bfloat162_rn(h0 - __bfloat162float(p01.x),
                                                           h1 - __bfloat162float(p01.y));
                __nv_bfloat162 q23 = __floats2bfloat162_rn(h2 - __bfloat162float(p23.x),
                                                           h3 - __bfloat162float(p23.y));
                __nv_bfloat162 q45 = __floats2bfloat162_rn(h4 - __bfloat162float(p45.x),
                                                           h5 - __bfloat162float(p45.y));
                __nv_bfloat162 q67 = __floats2bfloat162_rn(h6 - __bfloat162float(p67.x),
                                                           h7 - __bfloat162float(p67.y));
                uint4 lo4;
                lo4.x = *(uint32_t*)&q01; lo4.y = *(uint32_t*)&q23;
                lo4.z = *(uint32_t*)&q45; lo4.w = *(uint32_t*)&q67;
                oh[u] = hi4;
                ol[u] = lo4;
            }
        }
        __syncthreads();

        float acc[16][4];
#pragma unroll
        for (int nt = 0; nt < 16; nt++)
#pragma unroll
            for (int i = 0; i < 4; i++) acc[nt][i] = 0.f;

        int r0 = warp * 16;
#pragma unroll 1
        for (int s = 0; s < 3; s++) {
            const uint32_t* A  = (s == 2) ? H1lo : H1hi;
            const uint32_t* Bm = (s == 1) ? W2lo : W2hi;
#pragma unroll
            for (int kt = 0; kt < 8; kt++) {
                uint32_t a0 = A[(r0 + g)     * STRA + 8 * kt + tig];
                uint32_t a1 = A[(r0 + g + 8) * STRA + 8 * kt + tig];
                uint32_t a2 = A[(r0 + g)     * STRA + 8 * kt + 4 + tig];
                uint32_t a3 = A[(r0 + g + 8) * STRA + 8 * kt + 4 + tig];
#pragma unroll
                for (int nt = 0; nt < 16; nt++) {
                    uint32_t b0 = Bm[(8 * nt + g) * STRA + 8 * kt + tig];
                    uint32_t b1 = Bm[(8 * nt + g) * STRA + 8 * kt + 4 + tig];
                    asm volatile(
                        "mma.sync.aligned.m16n8k16.row.col.f32.bf16.bf16.f32 "
                        "{%0,%1,%2,%3}, {%4,%5,%6,%7}, {%8,%9}, {%0,%1,%2,%3};"
                        : "+f"(acc[nt][0]), "+f"(acc[nt][1]),
                          "+f"(acc[nt][2]), "+f"(acc[nt][3])
                        : "r"(a0), "r"(a1), "r"(a2), "r"(a3), "r"(b0), "r"(b1));
                }
            }
        }

        int p0 = tile * 16 + warp * 2;
#pragma unroll
        for (int nt = 0; nt < 16; nt++) {
            float bb0 = b2s[8 * nt + 2 * tig], bb1 = b2s[8 * nt + 2 * tig + 1];
            float v0 = fmaxf(acc[nt][0] + bb0, 0.f);
            float v1 = fmaxf(acc[nt][1] + bb1, 0.f);
            float v2 = fmaxf(acc[nt][2] + bb0, 0.f);
            float v3 = fmaxf(acc[nt][3] + bb1, 0.f);
#pragma unroll
            for (int off = 4; off <= 16; off <<= 1) {
                v0 += __shfl_xor_sync(0xffffffffu, v0, off);
                v1 += __shfl_xor_sync(0xffffffffu, v1, off);
                v2 += __shfl_xor_sync(0xffffffffu, v2, off);
                v3 += __shfl_xor_sync(0xffffffffu, v3, off);
            }
            if (lane < 4) {
                int col = 8 * nt + 2 * tig;
                float2* o0 = (float2*)(xout + (size_t)p0 * 128 + col);
                float2* o1 = (float2*)(xout + (size_t)(p0 + 1) * 128 + col);
                *o0 = make_float2(v0 * 0.125f, v1 * 0.125f);
                *o1 = make_float2(v2 * 0.125f, v3 * 0.125f);
            }
        }
        __syncthreads();
    }
}

// ---------------- mean pool, stage 1 ----------------
__global__ void poolp_kernel(const float* __restrict__ x1, const float* __restrict__ x2,
                             const float* __restrict__ x3) {
    int b = blockIdx.y, chunk = blockIdx.x;
    int c = threadIdx.x;
    const float* src = (c < 128) ? x1 : ((c < 256) ? x2 : x3);
    int cc = c & 127;
    int p0 = chunk * 256;
    float s = 0.f;
    for (int p = p0; p < p0 + 256; p++) s += src[((size_t)b * P_ + p) * H_ + cc];
    g_poolp[(b * 8 + chunk) * 384 + c] = s;
}

// ---------------- mean pool, stage 2 ----------------
__global__ void poolr_kernel(float* __restrict__ pooled) {
    int b = blockIdx.x;
    int c = threadIdx.x;
    float s = 0.f;
#pragma unroll
    for (int k = 0; k < 8; k++) s += g_poolp[(b * 8 + k) * 384 + c];
    pooled[b * 384 + c] = s * (1.f / (float)P_);
}

// ---------------- head MLP ----------------
__global__ void head_kernel(const float* __restrict__ pooled,
                            const float* __restrict__ W1, const float* __restrict__ b1,
                            const float* __restrict__ W2, const float* __restrict__ b2,
                            float* __restrict__ out) {
    int b = blockIdx.x;
    int h = threadIdx.x;
    __shared__ float v[128];
    float t = b1[h];
    for (int c = 0; c < 384; c++) t = fmaf(pooled[b * 384 + c], W1[c * 128 + h], t);
    v[h] = fmaxf(t, 0.f);
    __syncthreads();
    if (h < 2) {
        float o = b2[h];
        for (int d = 0; d < 128; d++) o = fmaf(v[d], W2[d * 2 + h], o);
        out[b * 2 + h] = o;
    }
}

// ---------------- launch ----------------
extern "C" void kernel_launch(void* const* d_in, const int* in_sizes, int n_in,
                              void* d_out, int out_size) {
    const float* x     = (const float*)d_in[0];
    const float* c1W1  = (const float*)d_in[1];
    const float* c1b1  = (const float*)d_in[2];
    const float* c1W2  = (const float*)d_in[3];
    const float* c1b2  = (const float*)d_in[4];
    const float* c2W1  = (const float*)d_in[5];
    const float* c2b1  = (const float*)d_in[6];
    const float* c2W2  = (const float*)d_in[7];
    const float* c2b2  = (const float*)d_in[8];
    const float* c3W1  = (const float*)d_in[9];
    const float* c3b1  = (const float*)d_in[10];
    const float* c3W2  = (const float*)d_in[11];
    const float* c3b2  = (const float*)d_in[12];
    const float* mW1   = (const float*)d_in[13];
    const float* mb1   = (const float*)d_in[14];
    const float* mW2   = (const float*)d_in[15];
    const float* mb2   = (const float*)d_in[16];
    float* out = (float*)d_out;

    float *x1, *x2, *x3, *T, *Y, *sqv, *pool;
    int* idxv;
    cudaGetSymbolAddress((void**)&x1,   g_x1);
    cudaGetSymbolAddress((void**)&x2,   g_x2);
    cudaGetSymbolAddress((void**)&x3,   g_x3);
    cudaGetSymbolAddress((void**)&T,    g_T);
    cudaGetSymbolAddress((void**)&Y,    g_Y);
    cudaGetSymbolAddress((void**)&sqv,  g_sq);
    cudaGetSymbolAddress((void**)&idxv, g_idx);
    cudaGetSymbolAddress((void**)&pool, g_pool);

    const int PRE_SMEM  = PRE_SMEM_FLOATS * (int)sizeof(float);
    cudaFuncSetAttribute(knn128_sym_kernel, cudaFuncAttributeMaxDynamicSharedMemorySize, KNN_SMEM_BYTES);
    cudaFuncSetAttribute(pre128_kernel,     cudaFuncAttributeMaxDynamicSharedMemorySize, PRE_SMEM);
    cudaFuncSetAttribute(edgemma_kernel,    cudaFuncAttributeMaxDynamicSharedMemorySize, EDGE_SMEM_BYTES);

    const int EDGE_GRID = 148;   // persistent: 1 block/SM, tile-stride loop

    // ---- layer 1 (D=3) ----
    sqnorm_kernel<<<NPTS / 8, 256>>>(x, sqv, 3, NPTS);
    knn3_kernel<<<dim3(P_ / 256, B_), 256>>>(x, sqv, idxv);
    pre3_kernel<<<NPTS / 8, 256>>>(x, c1W1, c1b1, T, Y);
    edgemma_kernel<<<EDGE_GRID, 256, EDGE_SMEM_BYTES>>>(T, Y, idxv, c1W2, c1b2, x1);

    // ---- layer 2 (D=128) ----
    sqnorm_kernel<<<NPTS / 8, 256>>>(x1, sqv, 128, NPTS);
    knn128_sym_kernel<<<dim3(NPAIR, B_), 256, KNN_SMEM_BYTES>>>(x1, sqv);
    knnmerge_kernel<<<NPTS / 256, 256>>>(idxv);
    pre128_kernel<<<NPTS / 128, 512, PRE_SMEM>>>(x1, c2W1, c2b1, T, Y);
    edgemma_kernel<<<EDGE_GRID, 256, EDGE_SMEM_BYTES>>>(T, Y, idxv, c2W2, c2b2, x2);

    // ---- layer 3 (D=128) ----
    sqnorm_kernel<<<NPTS / 8, 256>>>(x2, sqv, 128, NPTS);
    knn128_sym_kernel<<<dim3(NPAIR, B_), 256, KNN_SMEM_BYTES>>>(x2, sqv);
    knnmerge_kernel<<<NPTS / 256, 256>>>(idxv);
    pre128_kernel<<<NPTS / 128, 512, PRE_SMEM>>>(x2, c3W1, c3b1, T, Y);
    edgemma_kernel<<<EDGE_GRID, 256, EDGE_SMEM_BYTES>>>(T, Y, idxv, c3W2, c3b2, x3);

    // ---- pool + head ----
    poolp_kernel<<<dim3(8, B_), 384>>>(x1, x2, x3);
    poolr_kernel<<<B_, 384>>>(pool);
    head_kernel<<<B_, 128>>>(pool, mW1, mb1, mW2, mb2, out);
}

// round 16
// speedup vs baseline: 1.7002x; 1.7002x over previous
#include <cuda_runtime.h>
#include <cuda_bf16.h>
#include <cstdint>

#define B_  16
#define P_  2048
#define H_  128
#define K_  8
#define NPTS (B_ * P_)
#define NTILE 32              // P_/64 candidate tiles per batch
#define NPAIR 528             // NTILE*(NTILE+1)/2

// ---------------- scratch (no allocations allowed) ----------------
__device__ float  g_x1[NPTS * H_];
__device__ float  g_x2[NPTS * H_];
__device__ float  g_x3[NPTS * H_];
__device__ float  g_T [NPTS * H_];
__device__ float  g_Y [NPTS * H_];
__device__ float  g_sq[NPTS];
__device__ int    g_idx[NPTS * K_];
__device__ float2 g_part[(size_t)NPTS * NTILE * K_];   // per (query, tile) partial top-8
__device__ float  g_poolp[B_ * 8 * 3 * H_];
__device__ float  g_pool[B_ * 3 * H_];

// ---------------- top-8 (smallest d2, tie -> lower index) ----------------
__device__ __forceinline__ void top8_init(float* bd, int* bi) {
#pragma unroll
    for (int m = 0; m < 8; m++) { bd[m] = __int_as_float(0x7f800000); bi[m] = 0x7fffffff; }
}

__device__ __forceinline__ void top8_insert(float* bd, int* bi, float d, int j) {
    if (d < bd[7] || (d == bd[7] && j < bi[7])) {
        bd[7] = d; bi[7] = j;
#pragma unroll
        for (int m = 7; m > 0; m--) {
            bool sw = (bd[m] < bd[m - 1]) || (bd[m] == bd[m - 1] && bi[m] < bi[m - 1]);
            if (!sw) break;
            float td = bd[m]; bd[m] = bd[m - 1]; bd[m - 1] = td;
            int   tj = bi[m]; bi[m] = bi[m - 1]; bi[m - 1] = tj;
        }
    }
}

// ---------------- squared norms (one warp per point) ----------------
__global__ void sqnorm_kernel(const float* __restrict__ X, float* __restrict__ sq,
                              int D, int npts) {
    int gw = (blockIdx.x * blockDim.x + threadIdx.x) >> 5;
    int lane = threadIdx.x & 31;
    if (gw >= npts) return;
    const float* xp = X + (size_t)gw * D;
    float s = 0.f;
    for (int d = lane; d < D; d += 32) { float v = xp[d]; s = fmaf(v, v, s); }
#pragma unroll
    for (int o = 16; o > 0; o >>= 1) s += __shfl_xor_sync(0xffffffffu, s, o);
    if (lane == 0) sq[gw] = s;
}

// ---------------- kNN for D=3 (one thread per query) ----------------
__global__ __launch_bounds__(256) void knn3_kernel(const float* __restrict__ X,
                                                   const float* __restrict__ sq,
                                                   int* __restrict__ idx) {
    int b = blockIdx.y;
    int q = blockIdx.x * 256 + threadIdx.x;
    const float* Xb  = X  + (size_t)b * P_ * 3;
    const float* sqb = sq + (size_t)b * P_;
    float qx = Xb[q * 3 + 0], qy = Xb[q * 3 + 1], qz = Xb[q * 3 + 2];
    float sqq = sqb[q];
    float bd[8]; int bi[8]; top8_init(bd, bi);
    __shared__ float cs[256][4];
    for (int t = 0; t < P_; t += 256) {
        int tt = threadIdx.x;
        cs[tt][0] = Xb[(t + tt) * 3 + 0];
        cs[tt][1] = Xb[(t + tt) * 3 + 1];
        cs[tt][2] = Xb[(t + tt) * 3 + 2];
        cs[tt][3] = sqb[t + tt];
        __syncthreads();
        for (int jj = 0; jj < 256; jj++) {
            float dot = qx * cs[jj][0] + qy * cs[jj][1] + qz * cs[jj][2];
            float d = sqq + cs[jj][3] - 2.f * dot;
            top8_insert(bd, bi, d, t + jj);
        }
        __syncthreads();
    }
    int* op = idx + ((size_t)b * P_ + q) * K_;
#pragma unroll
    for (int m = 0; m < 8; m++) op[m] = bi[m];
}

// ---------------- symmetric kNN for D=128 (scalar, proven R12/R14 version) ------
#define KNN_SMEM_FLOATS (128*68 + 32*68 + 64*65 + 64 + 64)
__global__ __launch_bounds__(256) void knn128_sym_kernel(const float* __restrict__ X,
                                                         const float* __restrict__ sq) {
    extern __shared__ float sm[];
    float* Qs  = sm;                       // [d][q] stride 68
    float* Cs  = Qs + 128 * 68;            // [d][c] stride 68
    float* d2s = Cs + 32 * 68;             // [q][c] stride 65
    float* qsq = d2s + 64 * 65;
    float* csq = qsq + 64;
    float* md  = Qs;                       // overlay
    int*   mi  = (int*)(Qs + 2048);        // overlay
    float4* Qs4 = (float4*)Qs;
    float4* Cs4 = (float4*)Cs;

    int b = blockIdx.y;
    int lin = blockIdx.x, qt = 0;
    while (true) { int cnt = NTILE - qt; if (lin < cnt) break; lin -= cnt; qt++; }
    int ct = qt + lin;
    int q0 = qt * 64, c0 = ct * 64;

    int tid = threadIdx.x;
    int tx = tid & 15, ty = tid >> 4;
    const float* Xb  = X  + (size_t)b * P_ * 128;
    const float* sqb = sq + (size_t)b * P_;

    for (int e = tid; e < 64 * 128; e += 256) {
        int q = e >> 7, d = e & 127;
        Qs[d * 68 + q] = Xb[(q0 + q) * 128 + d];
    }
    if (tid < 64)       qsq[tid]      = sqb[q0 + tid];
    else if (tid < 128) csq[tid - 64] = sqb[c0 + tid - 64];
    __syncthreads();

    float4 acc0 = {0,0,0,0}, acc1 = {0,0,0,0}, acc2 = {0,0,0,0}, acc3 = {0,0,0,0};
    for (int dc = 0; dc < 128; dc += 32) {
        for (int e = tid; e < 2048; e += 256) {
            int c = e >> 5, d = e & 31;
            Cs[d * 68 + c] = Xb[(c0 + c) * 128 + dc + d];
        }
        __syncthreads();
#pragma unroll
        for (int kk = 0; kk < 32; kk++) {
            float4 qv = Qs4[(dc + kk) * 17 + ty];
            float4 cv = Cs4[kk * 17 + tx];
            acc0.x = fmaf(qv.x, cv.x, acc0.x); acc0.y = fmaf(qv.x, cv.y, acc0.y);
            acc0.z = fmaf(qv.x, cv.z, acc0.z); acc0.w = fmaf(qv.x, cv.w, acc0.w);
            acc1.x = fmaf(qv.y, cv.x, acc1.x); acc1.y = fmaf(qv.y, cv.y, acc1.y);
            acc1.z = fmaf(qv.y, cv.z, acc1.z); acc1.w = fmaf(qv.y, cv.w, acc1.w);
            acc2.x = fmaf(qv.z, cv.x, acc2.x); acc2.y = fmaf(qv.z, cv.y, acc2.y);
            acc2.z = fmaf(qv.z, cv.z, acc2.z); acc2.w = fmaf(qv.z, cv.w, acc2.w);
            acc3.x = fmaf(qv.w, cv.x, acc3.x); acc3.y = fmaf(qv.w, cv.y, acc3.y);
            acc3.z = fmaf(qv.w, cv.z, acc3.z); acc3.w = fmaf(qv.w, cv.w, acc3.w);
        }
        __syncthreads();
    }
    {
        int qb = ty * 4, cb = tx * 4;
        float* r0 = d2s + (qb + 0) * 65 + cb;
        float* r1 = d2s + (qb + 1) * 65 + cb;
        float* r2 = d2s + (qb + 2) * 65 + cb;
        float* r3 = d2s + (qb + 3) * 65 + cb;
        r0[0] = acc0.x; r0[1] = acc0.y; r0[2] = acc0.z; r0[3] = acc0.w;
        r1[0] = acc1.x; r1[1] = acc1.y; r1[2] = acc1.z; r1[3] = acc1.w;
        r2[0] = acc2.x; r2[1] = acc2.y; r2[2] = acc2.z; r2[3] = acc2.w;
        r3[0] = acc3.x; r3[1] = acc3.y; r3[2] = acc3.z; r3[3] = acc3.w;
    }
    __syncthreads();

    int q_s = tid >> 2, sl = tid & 3;
    {
        float bd[8]; int bi8[8]; top8_init(bd, bi8);
        float sqq = qsq[q_s];
#pragma unroll
        for (int u = 0; u < 16; u++) {
            int c = sl * 16 + u;
            float d = sqq + csq[c] - 2.f * d2s[q_s * 65 + c];
            top8_insert(bd, bi8, d, c0 + c);
        }
        int base = q_s * 32 + sl * 8;
#pragma unroll
        for (int m = 0; m < 8; m++) { md[base + m] = bd[m]; mi[base + m] = bi8[m]; }
    }
    __syncthreads();
    if (sl == 0) {
        float fd[8]; int fi[8]; top8_init(fd, fi);
        for (int e = 0; e < 32; e++) top8_insert(fd, fi, md[q_s * 32 + e], mi[q_s * 32 + e]);
        float2* gp = g_part + ((size_t)(b * P_ + q0 + q_s) * NTILE + ct) * K_;
#pragma unroll
        for (int m = 0; m < 8; m++) gp[m] = make_float2(fd[m], __int_as_float(fi[m]));
    }

    if (ct != qt) {
        __syncthreads();
        {
            float bd[8]; int bi8[8]; top8_init(bd, bi8);
            float sqq = csq[q_s];
#pragma unroll
            for (int u = 0; u < 16; u++) {
                int r = sl * 16 + u;
                float d = sqq + qsq[r] - 2.f * d2s[r * 65 + q_s];
                top8_insert(bd, bi8, d, q0 + r);
            }
            int base = q_s * 32 + sl * 8;
#pragma unroll
            for (int m = 0; m < 8; m++) { md[base + m] = bd[m]; mi[base + m] = bi8[m]; }
        }
        __syncthreads();
        if (sl == 0) {
            float fd[8]; int fi[8]; top8_init(fd, fi);
            for (int e = 0; e < 32; e++) top8_insert(fd, fi, md[q_s * 32 + e], mi[q_s * 32 + e]);
            float2* gp = g_part + ((size_t)(b * P_ + c0 + q_s) * NTILE + qt) * K_;
#pragma unroll
            for (int m = 0; m < 8; m++) gp[m] = make_float2(fd[m], __int_as_float(fi[m]));
        }
    }
}

// ---------------- merge partial top-8 lists ----------------
__global__ __launch_bounds__(256) void knnmerge_kernel(int* __restrict__ idx) {
    int q = blockIdx.x * 256 + threadIdx.x;
    const float2* pp = g_part + (size_t)q * (NTILE * K_);
    float bd[8]; int bi8[8]; top8_init(bd, bi8);
    for (int e = 0; e < NTILE * K_; e++) {
        float2 v = pp[e];
        top8_insert(bd, bi8, v.x, __float_as_int(v.y));
    }
    int* op = idx + (size_t)q * K_;
#pragma unroll
    for (int m = 0; m < 8; m++) op[m] = bi8[m];
}

// ---------------- pretransform, D=3 ----------------
__global__ __launch_bounds__(256) void pre3_kernel(const float* __restrict__ x,
                                                   const float* __restrict__ W1,
                                                   const float* __restrict__ b1,
                                                   float* __restrict__ T,
                                                   float* __restrict__ Y) {
    int p = blockIdx.x * 8 + (threadIdx.x >> 5);
    int l = threadIdx.x & 31;
    const float4* W14 = (const float4*)W1;
    float4 t = ((const float4*)b1)[l];
    float4 y = {0.f, 0.f, 0.f, 0.f};
#pragma unroll
    for (int r = 0; r < 3; r++) {
        float  xr  = x[p * 3 + r];
        float4 whi = W14[r * 32 + l];
        float4 wlo = W14[(3 + r) * 32 + l];
        t.x = fmaf(xr, whi.x - wlo.x, t.x); t.y = fmaf(xr, whi.y - wlo.y, t.y);
        t.z = fmaf(xr, whi.z - wlo.z, t.z); t.w = fmaf(xr, whi.w - wlo.w, t.w);
        y.x = fmaf(xr, wlo.x, y.x); y.y = fmaf(xr, wlo.y, y.y);
        y.z = fmaf(xr, wlo.z, y.z); y.w = fmaf(xr, wlo.w, y.w);
    }
    ((float4*)T)[p * 32 + l] = t;
    ((float4*)Y)[p * 32 + l] = y;
}

// ---------------- pretransform, D=128 (unchanged) ----------------
#define PRE_SMEM_FLOATS (16384 + 16384 + 16 * 1024)
__global__ __launch_bounds__(512) void pre128_kernel(const float* __restrict__ xin,
                                                     const float* __restrict__ W1,
                                                     const float* __restrict__ b1,
                                                     float* __restrict__ T,
                                                     float* __restrict__ Y) {
    extern __shared__ float sm[];
    float* Wds  = sm;
    float* Wlos = Wds + 16384;
    float* Xs   = Wlos + 16384;
    int tid = threadIdx.x;
    int warp = tid >> 5, lane = tid & 31;

    for (int e = tid; e < 16384; e += 512) {
        float hi = W1[e], lo = W1[16384 + e];
        Wds[e] = hi - lo; Wlos[e] = lo;
    }
    int p0 = blockIdx.x * 128 + warp * 8;
    float4* Xw4 = (float4*)(Xs + warp * 1024);
#pragma unroll
    for (int e = 0; e < 8; e++)
        Xw4[e * 32 + lane] = ((const float4*)xin)[(size_t)(p0 + e) * 32 + lane];
    __syncthreads();

    const float4* Wd4  = (const float4*)Wds;
    const float4* Wl4  = (const float4*)Wlos;
    const float4* Xf4  = (const float4*)(Xs + warp * 1024);

#pragma unroll 1
    for (int pass = 0; pass < 2; pass++) {
        const float4* W4 = pass ? Wl4 : Wd4;
        float4 acc[8];
#pragma unroll
        for (int e = 0; e < 8; e++) acc[e] = make_float4(0.f, 0.f, 0.f, 0.f);
        for (int d0 = 0; d0 < 128; d0 += 4) {
            float4 w0 = W4[(d0 + 0) * 32 + lane];
            float4 w1 = W4[(d0 + 1) * 32 + lane];
            float4 w2 = W4[(d0 + 2) * 32 + lane];
            float4 w3 = W4[(d0 + 3) * 32 + lane];
#pragma unroll
            for (int e = 0; e < 8; e++) {
                float4 h = Xf4[e * 32 + (d0 >> 2)];
                acc[e].x = fmaf(h.x, w0.x, acc[e].x); acc[e].y = fmaf(h.x, w0.y, acc[e].y);
                acc[e].z = fmaf(h.x, w0.z, acc[e].z); acc[e].w = fmaf(h.x, w0.w, acc[e].w);
                acc[e].x = fmaf(h.y, w1.x, acc[e].x); acc[e].y = fmaf(h.y, w1.y, acc[e].y);
                acc[e].z = fmaf(h.y, w1.z, acc[e].z); acc[e].w = fmaf(h.y, w1.w, acc[e].w);
                acc[e].x = fmaf(h.z, w2.x, acc[e].x); acc[e].y = fmaf(h.z, w2.y, acc[e].y);
                acc[e].z = fmaf(h.z, w2.z, acc[e].z); acc[e].w = fmaf(h.z, w2.w, acc[e].w);
                acc[e].x = fmaf(h.w, w3.x, acc[e].x); acc[e].y = fmaf(h.w, w3.y, acc[e].y);
                acc[e].z = fmaf(h.w, w3.z, acc[e].z); acc[e].w = fmaf(h.w, w3.w, acc[e].w);
            }
        }
        if (pass == 0) {
            float4 bb = ((const float4*)b1)[lane];
#pragma unroll
            for (int e = 0; e < 8; e++) {
                float4 o; o.x = acc[e].x + bb.x; o.y = acc[e].y + bb.y;
                o.z = acc[e].z + bb.z; o.w = acc[e].w + bb.w;
                ((float4*)T)[(size_t)(p0 + e) * 32 + lane] = o;
            }
        } else {
#pragma unroll
            for (int e = 0; e < 8; e++)
                ((float4*)Y)[(size_t)(p0 + e) * 32 + lane] = acc[e];
        }
    }
}

// ---------------- edge MLP2 via mma.sync, A-side bf16, W2 hi+lo split ----------
// D = Ahi*(Bhi + Blo), fp32 acc. H1 rounding error is random per point -> pools
// away (~1e-5 at output); W2 split keeps weight error compensated (systematic).
// smem 105.5 KB -> 2 blocks/SM (16 warps/SM).
#define STRA 68     // uint32 words per smem row (136 bf16)
#define EDGE_SMEM_BYTES (1024 + 3 * 128 * STRA * 4)   // sidx+b2 | W2hi W2lo H1hi
__global__ __launch_bounds__(256) void edgemma_kernel(const float* __restrict__ T,
                                                      const float* __restrict__ Y,
                                                      const int* __restrict__ idx,
                                                      const float* __restrict__ W2,
                                                      const float* __restrict__ b2,
                                                      float* __restrict__ xout) {
    extern __shared__ float sm[];
    int*      sidx = (int*)sm;                    // 128 ints
    float*    b2s  = sm + 128;                    // 128 floats
    uint32_t* W2hi = (uint32_t*)(sm + 256);       // [c][k] 128 x 68 words
    uint32_t* W2lo = W2hi + 128 * STRA;
    uint32_t* H1hi = W2lo + 128 * STRA;           // [r][k]

    int tid = threadIdx.x, warp = tid >> 5, lane = tid & 31;
    int g = lane >> 2, tig = lane & 3;

    if (tid < 128) b2s[tid] = b2[tid];
    for (int e = tid; e < 16384; e += 256) {
        int d = e >> 7, c = e & 127;
        float v = W2[e];
        __nv_bfloat16 bh = __float2bfloat16(v);
        __nv_bfloat16 bl = __float2bfloat16(v - __bfloat162float(bh));
        ((__nv_bfloat16*)W2hi)[c * 136 + d] = bh;
        ((__nv_bfloat16*)W2lo)[c * 136 + d] = bl;
    }
    __syncthreads();

#pragma unroll 1
    for (int tile = blockIdx.x; tile < NPTS / 16; tile += gridDim.x) {
        if (tid < 128) sidx[tid] = idx[tile * 128 + tid];
        __syncthreads();

        // ---- build H1 (bf16): row r = pl*8+e, h[d] = relu(T[p][d] + Y[base+j][d]) --
        {
            int r = tid >> 1, half = tid & 1;
            int j = sidx[r];
            int p = tile * 16 + (r >> 3);
            int base = p & ~(P_ - 1);
            const float4* Tp = (const float4*)(T + (size_t)p * 128 + half * 64);
            const float4* Yp = (const float4*)(Y + (size_t)(base + j) * 128 + half * 64);
            uint4* oh = (uint4*)((__nv_bfloat16*)H1hi + r * 136 + half * 64);
#pragma unroll
            for (int u = 0; u < 8; u++) {
                float4 ta = Tp[2 * u], tb = Tp[2 * u + 1];
                float4 ya = Yp[2 * u], yb = Yp[2 * u + 1];
                __nv_bfloat162 p01 = __floats2bfloat162_rn(fmaxf(ta.x + ya.x, 0.f),
                                                           fmaxf(ta.y + ya.y, 0.f));
                __nv_bfloat162 p23 = __floats2bfloat162_rn(fmaxf(ta.z + ya.z, 0.f),
                                                           fmaxf(ta.w + ya.w, 0.f));
                __nv_bfloat162 p45 = __floats2bfloat162_rn(fmaxf(tb.x + yb.x, 0.f),
                                                           fmaxf(tb.y + yb.y, 0.f));
                __nv_bfloat162 p67 = __floats2bfloat162_rn(fmaxf(tb.z + yb.z, 0.f),
                                                           fmaxf(tb.w + yb.w, 0.f));
                uint4 hi4;
                hi4.x = *(uint32_t*)&p01; hi4.y = *(uint32_t*)&p23;
                hi4.z = *(uint32_t*)&p45; hi4.w = *(uint32_t*)&p67;
                oh[u] = hi4;
            }
        }
        __syncthreads();

        // ---- MMA: warp rows r0 = warp*16; D = Ahi*Bhi + Ahi*Blo ----
        float acc[16][4];
#pragma unroll
        for (int nt = 0; nt < 16; nt++)
#pragma unroll
            for (int i = 0; i < 4; i++) acc[nt][i] = 0.f;

        int r0 = warp * 16;
#pragma unroll 1
        for (int s = 0; s < 2; s++) {
            const uint32_t* A  = H1hi;
            const uint32_t* Bm = s ? W2lo : W2hi;
#pragma unroll
            for (int kt = 0; kt < 8; kt++) {
                uint32_t a0 = A[(r0 + g)     * STRA + 8 * kt + tig];
                uint32_t a1 = A[(r0 + g + 8) * STRA + 8 * kt + tig];
                uint32_t a2 = A[(r0 + g)     * STRA + 8 * kt + 4 + tig];
                uint32_t a3 = A[(r0 + g + 8) * STRA + 8 * kt + 4 + tig];
#pragma unroll
                for (int nt = 0; nt < 16; nt++) {
                    uint32_t b0 = Bm[(8 * nt + g) * STRA + 8 * kt + tig];
                    uint32_t b1 = Bm[(8 * nt + g) * STRA + 8 * kt + 4 + tig];
                    asm volatile(
                        "mma.sync.aligned.m16n8k16.row.col.f32.bf16.bf16.f32 "
                        "{%0,%1,%2,%3}, {%4,%5,%6,%7}, {%8,%9}, {%0,%1,%2,%3};"
                        : "+f"(acc[nt][0]), "+f"(acc[nt][1]),
                          "+f"(acc[nt][2]), "+f"(acc[nt][3])
                        : "r"(a0), "r"(a1), "r"(a2), "r"(a3), "r"(b0), "r"(b1));
                }
            }
        }

        // ---- epilogue: relu(D + b2), mean over 8 edges (reduce over g) ----
        int p0 = tile * 16 + warp * 2;
#pragma unroll
        for (int nt = 0; nt < 16; nt++) {
            float bb0 = b2s[8 * nt + 2 * tig], bb1 = b2s[8 * nt + 2 * tig + 1];
            float v0 = fmaxf(acc[nt][0] + bb0, 0.f);
            float v1 = fmaxf(acc[nt][1] + bb1, 0.f);
            float v2 = fmaxf(acc[nt][2] + bb0, 0.f);
            float v3 = fmaxf(acc[nt][3] + bb1, 0.f);
#pragma unroll
            for (int off = 4; off <= 16; off <<= 1) {
                v0 += __shfl_xor_sync(0xffffffffu, v0, off);
                v1 += __shfl_xor_sync(0xffffffffu, v1, off);
                v2 += __shfl_xor_sync(0xffffffffu, v2, off);
                v3 += __shfl_xor_sync(0xffffffffu, v3, off);
            }
            if (lane < 4) {
                int col = 8 * nt + 2 * tig;
                float2* o0 = (float2*)(xout + (size_t)p0 * 128 + col);
                float2* o1 = (float2*)(xout + (size_t)(p0 + 1) * 128 + col);
                *o0 = make_float2(v0 * 0.125f, v1 * 0.125f);
                *o1 = make_float2(v2 * 0.125f, v3 * 0.125f);
            }
        }
        __syncthreads();
    }
}

// ---------------- mean pool, stage 1 ----------------
__global__ void poolp_kernel(const float* __restrict__ x1, const float* __restrict__ x2,
                             const float* __restrict__ x3) {
    int b = blockIdx.y, chunk = blockIdx.x;
    int c = threadIdx.x;
    const float* src = (c < 128) ? x1 : ((c < 256) ? x2 : x3);
    int cc = c & 127;
    int p0 = chunk * 256;
    float s = 0.f;
    for (int p = p0; p < p0 + 256; p++) s += src[((size_t)b * P_ + p) * H_ + cc];
    g_poolp[(b * 8 + chunk) * 384 + c] = s;
}

// ---------------- mean pool, stage 2 ----------------
__global__ void poolr_kernel(float* __restrict__ pooled) {
    int b = blockIdx.x;
    int c = threadIdx.x;
    float s = 0.f;
#pragma unroll
    for (int k = 0; k < 8; k++) s += g_poolp[(b * 8 + k) * 384 + c];
    pooled[b * 384 + c] = s * (1.f / (float)P_);
}

// ---------------- head MLP ----------------
__global__ void head_kernel(const float* __restrict__ pooled,
                            const float* __restrict__ W1, const float* __restrict__ b1,
                            const float* __restrict__ W2, const float* __restrict__ b2,
                            float* __restrict__ out) {
    int b = blockIdx.x;
    int h = threadIdx.x;
    __shared__ float v[128];
    float t = b1[h];
    for (int c = 0; c < 384; c++) t = fmaf(pooled[b * 384 + c], W1[c * 128 + h], t);
    v[h] = fmaxf(t, 0.f);
    __syncthreads();
    if (h < 2) {
        float o = b2[h];
        for (int d = 0; d < 128; d++) o = fmaf(v[d], W2[d * 2 + h], o);
        out[b * 2 + h] = o;
    }
}

// ---------------- launch ----------------
extern "C" void kernel_launch(void* const* d_in, const int* in_sizes, int n_in,
                              void* d_out, int out_size) {
    const float* x     = (const float*)d_in[0];
    const float* c1W1  = (const float*)d_in[1];
    const float* c1b1  = (const float*)d_in[2];
    const float* c1W2  = (const float*)d_in[3];
    const float* c1b2  = (const float*)d_in[4];
    const float* c2W1  = (const float*)d_in[5];
    const float* c2b1  = (const float*)d_in[6];
    const float* c2W2  = (const float*)d_in[7];
    const float* c2b2  = (const float*)d_in[8];
    const float* c3W1  = (const float*)d_in[9];
    const float* c3b1  = (const float*)d_in[10];
    const float* c3W2  = (const float*)d_in[11];
    const float* c3b2  = (const float*)d_in[12];
    const float* mW1   = (const float*)d_in[13];
    const float* mb1   = (const float*)d_in[14];
    const float* mW2   = (const float*)d_in[15];
    const float* mb2   = (const float*)d_in[16];
    float* out = (float*)d_out;

    float *x1, *x2, *x3, *T, *Y, *sqv, *pool;
    int* idxv;
    cudaGetSymbolAddress((void**)&x1,   g_x1);
    cudaGetSymbolAddress((void**)&x2,   g_x2);
    cudaGetSymbolAddress((void**)&x3,   g_x3);
    cudaGetSymbolAddress((void**)&T,    g_T);
    cudaGetSymbolAddress((void**)&Y,    g_Y);
    cudaGetSymbolAddress((void**)&sqv,  g_sq);
    cudaGetSymbolAddress((void**)&idxv, g_idx);
    cudaGetSymbolAddress((void**)&pool, g_pool);

    const int KNN_SMEM  = KNN_SMEM_FLOATS * (int)sizeof(float);
    const int PRE_SMEM  = PRE_SMEM_FLOATS * (int)sizeof(float);
    cudaFuncSetAttribute(knn128_sym_kernel, cudaFuncAttributeMaxDynamicSharedMemorySize, KNN_SMEM);
    cudaFuncSetAttribute(pre128_kernel,     cudaFuncAttributeMaxDynamicSharedMemorySize, PRE_SMEM);
    cudaFuncSetAttribute(edgemma_kernel,    cudaFuncAttributeMaxDynamicSharedMemorySize, EDGE_SMEM_BYTES);

    const int EDGE_GRID = 296;   // persistent: 2 blocks/SM, tile-stride loop

    // ---- layer 1 (D=3) ----
    sqnorm_kernel<<<NPTS / 8, 256>>>(x, sqv, 3, NPTS);
    knn3_kernel<<<dim3(P_ / 256, B_), 256>>>(x, sqv, idxv);
    pre3_kernel<<<NPTS / 8, 256>>>(x, c1W1, c1b1, T, Y);
    edgemma_kernel<<<EDGE_GRID, 256, EDGE_SMEM_BYTES>>>(T, Y, idxv, c1W2, c1b2, x1);

    // ---- layer 2 (D=128) ----
    sqnorm_kernel<<<NPTS / 8, 256>>>(x1, sqv, 128, NPTS);
    knn128_sym_kernel<<<dim3(NPAIR, B_), 256, KNN_SMEM>>>(x1, sqv);
    knnmerge_kernel<<<NPTS / 256, 256>>>(idxv);
    pre128_kernel<<<NPTS / 128, 512, PRE_SMEM>>>(x1, c2W1, c2b1, T, Y);
    edgemma_kernel<<<EDGE_GRID, 256, EDGE_SMEM_BYTES>>>(T, Y, idxv, c2W2, c2b2, x2);

    // ---- layer 3 (D=128) ----
    sqnorm_kernel<<<NPTS / 8, 256>>>(x2, sqv, 128, NPTS);
    knn128_sym_kernel<<<dim3(NPAIR, B_), 256, KNN_SMEM>>>(x2, sqv);
    knnmerge_kernel<<<NPTS / 256, 256>>>(idxv);
    pre128_kernel<<<NPTS / 128, 512, PRE_SMEM>>>(x2, c3W1, c3b1, T, Y);
    edgemma_kernel<<<EDGE_GRID, 256, EDGE_SMEM_BYTES>>>(T, Y, idxv, c3W2, c3b2, x3);

    // ---- pool + head ----
    poolp_kernel<<<dim3(8, B_), 384>>>(x1, x2, x3);
    poolr_kernel<<<B_, 384>>>(pool);
    head_kernel<<<B_, 128>>>(pool, mW1, mb1, mW2, mb2, out);
}